// round 16
// baseline (speedup 1.0000x reference)
#include <cuda_runtime.h>
#include <cuda_bf16.h>
#include <cuda_fp16.h>
#include <cstdint>

// out = softmax(A @ W^T + b) @ E
// GEMM1/GEMM2: fp16 mma.sync, block 128x256x64, 16 warps, warp tile 32x64.
// Strength-reduced addressing, 3-stage cp.async ring, single barrier/k-step.

#define M_TOTAL 8192
#define D_DIM   1024
#define V_DIM   32000
#define E_DIM   4096
#define SHIFT   8.0f

// ---------------- device scratch -------------------------------------------
__device__ __align__(1024) __half g_p[(size_t)M_TOTAL * V_DIM];
__device__ __align__(1024) float g_sum[M_TOTAL];
__device__ __align__(1024) __half g_a16[(size_t)M_TOTAL * D_DIM];
__device__ __align__(1024) __half g_w16[(size_t)V_DIM * D_DIM];
__device__ __align__(1024) __half g_e16[(size_t)V_DIM * E_DIM];

// ---------------- PTX helpers ----------------------------------------------
__device__ __forceinline__ uint32_t smem_u32(const void* p) {
    return (uint32_t)__cvta_generic_to_shared(p);
}
__device__ __forceinline__ void cp16(uint32_t s, const void* g) {
    asm volatile("cp.async.cg.shared.global [%0], [%1], 16;\n" :: "r"(s), "l"(g));
}
__device__ __forceinline__ void cp_commit() {
    asm volatile("cp.async.commit_group;\n");
}
template<int N>
__device__ __forceinline__ void cp_wait() {
    asm volatile("cp.async.wait_group %0;\n" :: "n"(N));
}
__device__ __forceinline__ void ldsm4(uint32_t& r0, uint32_t& r1, uint32_t& r2, uint32_t& r3, uint32_t addr) {
    asm volatile("ldmatrix.sync.aligned.m8n8.x4.shared.b16 {%0,%1,%2,%3}, [%4];\n"
                 : "=r"(r0), "=r"(r1), "=r"(r2), "=r"(r3) : "r"(addr));
}
__device__ __forceinline__ void ldsm4t(uint32_t& r0, uint32_t& r1, uint32_t& r2, uint32_t& r3, uint32_t addr) {
    asm volatile("ldmatrix.sync.aligned.m8n8.x4.trans.shared.b16 {%0,%1,%2,%3}, [%4];\n"
                 : "=r"(r0), "=r"(r1), "=r"(r2), "=r"(r3) : "r"(addr));
}
__device__ __forceinline__ void mma_f16(float* d, const uint32_t* a, const uint32_t* b) {
    asm volatile("mma.sync.aligned.m16n8k16.row.col.f32.f16.f16.f32 "
                 "{%0,%1,%2,%3}, {%4,%5,%6,%7}, {%8,%9}, {%0,%1,%2,%3};\n"
                 : "+f"(d[0]), "+f"(d[1]), "+f"(d[2]), "+f"(d[3])
                 : "r"(a[0]), "r"(a[1]), "r"(a[2]), "r"(a[3]), "r"(b[0]), "r"(b[1]));
}

// ---------------- prep kernels ----------------------------------------------
__global__ __launch_bounds__(256) void conv_a16(
    const float4* __restrict__ src, __half2* __restrict__ dst, int n4)
{
    int b = blockIdx.x;
    int i = b * 256 + threadIdx.x;
    if (b < 32) g_sum[i] = 0.0f;
    if (i >= n4) return;
    float4 v = src[i];
    dst[2*i]   = __floats2half2_rn(v.x, v.y);
    dst[2*i+1] = __floats2half2_rn(v.z, v.w);
}

__global__ __launch_bounds__(256) void conv_f16(
    const float4* __restrict__ src, __half2* __restrict__ dst, int n4)
{
    int i = blockIdx.x * 256 + threadIdx.x;
    if (i >= n4) return;
    float4 v = src[i];
    dst[2*i]   = __floats2half2_rn(v.x, v.y);
    dst[2*i+1] = __floats2half2_rn(v.z, v.w);
}

// ---------------- GEMM1: 128x256x64, 16 warps, 32x64 warp tile, fp16 --------
#define G1_AS 72                       // 64 k + 8 pad (elems)
#define G1_APL (128 * G1_AS * 2)       // 18432
#define G1_BPL (256 * G1_AS * 2)       // 36864
#define G1_STAGE_B (G1_APL + G1_BPL)   // 55296
#define G1_STAGES 3
#define G1_SMEM (G1_STAGES * G1_STAGE_B + 512)

__global__ __launch_bounds__(512, 1) void gemm1_probs(const float* __restrict__ bias)
{
    extern __shared__ char smem[];
    float* srow = (float*)(smem + G1_STAGES * G1_STAGE_B);

    const int tid = threadIdx.x;
    const int lane = tid & 31;
    const int warp = tid >> 5;
    const int wm = warp >> 2;     // 0..3 (32 m)
    const int wn = warp & 3;      // 0..3 (64 n)

    const int NB = V_DIM / 256;   // 125
    const int bid = blockIdx.x;
    const int strip = bid / (8 * NB);
    const int r = bid % (8 * NB);
    const int bm = (strip * 8 + (r & 7)) * 128;
    const int bn = (r >> 3) * 256;

    if (tid < 128) srow[tid] = 0.0f;

    float acc[2][8][4];
    #pragma unroll
    for (int i = 0; i < 2; i++)
        #pragma unroll
        for (int j = 0; j < 8; j++)
            #pragma unroll
            for (int q = 0; q < 4; q++) acc[i][j][q] = 0.0f;

    // -------- hoisted addressing state --------
    uint32_t stb[G1_STAGES];
    #pragma unroll
    for (int s = 0; s < G1_STAGES; s++) stb[s] = smem_u32(smem) + s * G1_STAGE_B;

    // global pointers (advance += 64 elems per stage load); 512 threads
    const __half* gA[2];
    const __half* gW[4];
    uint32_t soA[2], soW[4];
    #pragma unroll
    for (int jj = 0; jj < 2; jj++) {
        int c = tid + jj * 512;
        int row = c >> 3;
        int cc = (c & 7) * 8;
        gA[jj]  = g_a16 + (size_t)(bm + row) * D_DIM + cc;
        soA[jj] = (uint32_t)(row * G1_AS + cc) * 2;
    }
    #pragma unroll
    for (int jj = 0; jj < 4; jj++) {
        int c = tid + jj * 512;
        int row = c >> 3;
        int cc = (c & 7) * 8;
        gW[jj]  = g_w16 + (size_t)(bn + row) * D_DIM + cc;
        soW[jj] = (uint32_t)(G1_APL + (row * G1_AS + cc) * 2);
    }

    auto load_stage = [&](int stg) {
        uint32_t sb = stb[stg];
        #pragma unroll
        for (int jj = 0; jj < 2; jj++) { cp16(sb + soA[jj], gA[jj]); gA[jj] += 64; }
        #pragma unroll
        for (int jj = 0; jj < 4; jj++) { cp16(sb + soW[jj], gW[jj]); gW[jj] += 64; }
    };

    // fragment smem offsets (const per thread)
    const int arow = wm * 32 + (lane & 15);
    const int brow = wn * 64 + (lane & 15);
    const int csel = (lane >> 4) * 8;
    uint32_t foA[2], foB[4];
    #pragma unroll
    for (int i = 0; i < 2; i++)
        foA[i] = (uint32_t)(((arow + i * 16) * G1_AS + csel) * 2);
    #pragma unroll
    for (int j = 0; j < 4; j++)
        foB[j] = (uint32_t)(G1_APL + ((brow + j * 16) * G1_AS + csel) * 2);

    const int KT = D_DIM / 64;   // 16
    load_stage(0);  cp_commit();
    load_stage(1);  cp_commit();

    for (int t = 0; t < KT; t++) {
        cp_wait<1>();
        __syncthreads();
        if (t + 2 < KT) load_stage((t + 2) % 3);
        cp_commit();

        uint32_t sb = stb[t % 3];
        #pragma unroll
        for (int kk = 0; kk < 4; kk++) {
            uint32_t ko = kk * 32;
            uint32_t a[2][4], b[8][2];
            #pragma unroll
            for (int i = 0; i < 2; i++)
                ldsm4(a[i][0], a[i][1], a[i][2], a[i][3], sb + foA[i] + ko);
            #pragma unroll
            for (int j = 0; j < 4; j++) {
                uint32_t r0, r1, r2, r3;
                ldsm4(r0, r1, r2, r3, sb + foB[j] + ko);
                b[2 * j][0] = r0;      b[2 * j + 1][0] = r1;
                b[2 * j][1] = r2;      b[2 * j + 1][1] = r3;
            }
            #pragma unroll
            for (int i = 0; i < 2; i++)
                #pragma unroll
                for (int j = 0; j < 8; j++)
                    mma_f16(acc[i][j], a[i], b[j]);
        }
    }
    __syncthreads();

    // fused epilogue: exp(logit - SHIFT) -> fp16 probs + row-sum atomics
    const int g = lane >> 2, tq = lane & 3;
    float bj0[8], bj1[8];
    #pragma unroll
    for (int j = 0; j < 8; j++) {
        int n = bn + wn * 64 + j * 8 + tq * 2;
        bj0[j] = bias[n];
        bj1[j] = bias[n + 1];
    }
    #pragma unroll
    for (int i = 0; i < 2; i++) {
        int ml0 = wm * 32 + i * 16 + g;
        float s0 = 0.0f, s1 = 0.0f;
        #pragma unroll
        for (int j = 0; j < 8; j++) {
            int n = bn + wn * 64 + j * 8 + tq * 2;
            float e0 = __expf(acc[i][j][0] + bj0[j] - SHIFT);
            float e1 = __expf(acc[i][j][1] + bj1[j] - SHIFT);
            float e2 = __expf(acc[i][j][2] + bj0[j] - SHIFT);
            float e3 = __expf(acc[i][j][3] + bj1[j] - SHIFT);
            s0 += e0 + e1;
            s1 += e2 + e3;
            *(__half2*)&g_p[(size_t)(bm + ml0) * V_DIM + n]     = __floats2half2_rn(e0, e1);
            *(__half2*)&g_p[(size_t)(bm + ml0 + 8) * V_DIM + n] = __floats2half2_rn(e2, e3);
        }
        s0 += __shfl_xor_sync(0xffffffff, s0, 1);
        s0 += __shfl_xor_sync(0xffffffff, s0, 2);
        s1 += __shfl_xor_sync(0xffffffff, s1, 1);
        s1 += __shfl_xor_sync(0xffffffff, s1, 2);
        if (tq == 0) {
            atomicAdd(&srow[ml0], s0);
            atomicAdd(&srow[ml0 + 8], s1);
        }
    }
    __syncthreads();
    if (tid < 128) atomicAdd(&g_sum[bm + tid], srow[tid]);
}

// ---------------- GEMM2: 128x256x64, 16 warps, 32x64 warp tile --------------
#define G2_AS 72
#define G2_APL (128 * G2_AS * 2)       // 18432
#define G2_BS 264                      // 256 n + 8 pad
#define G2_BPL (64 * G2_BS * 2)        // 33792
#define G2_STAGE_B (G2_APL + G2_BPL)   // 52224
#define G2_STAGES 3
#define G2_SMEM (G2_STAGES * G2_STAGE_B)

__global__ __launch_bounds__(512, 1) void gemm2_map(float* __restrict__ out)
{
    extern __shared__ char smem[];
    const int tid = threadIdx.x;
    const int lane = tid & 31;
    const int warp = tid >> 5;
    const int wm = warp >> 2;     // 0..3
    const int wn = warp & 3;      // 0..3

    const int bid = blockIdx.x;
    const int strip = bid >> 7;
    const int r = bid & 127;
    const int bm = (strip * 8 + (r & 7)) * 128;
    const int bn = (r >> 3) * 256;

    float acc[2][8][4];
    #pragma unroll
    for (int i = 0; i < 2; i++)
        #pragma unroll
        for (int j = 0; j < 8; j++)
            #pragma unroll
            for (int q = 0; q < 4; q++) acc[i][j][q] = 0.0f;

    // -------- hoisted addressing state --------
    uint32_t stb[G2_STAGES];
    #pragma unroll
    for (int s = 0; s < G2_STAGES; s++) stb[s] = smem_u32(smem) + s * G2_STAGE_B;

    const __half* gA[2];
    const __half* gB[4];
    uint32_t soA[2], soB[4];
    #pragma unroll
    for (int jj = 0; jj < 2; jj++) {   // A: 128 rows x 64 k (k-contig)
        int c = tid + jj * 512;
        int row = c >> 3;
        int cc = (c & 7) * 8;
        gA[jj]  = g_p + (size_t)(bm + row) * V_DIM + cc;
        soA[jj] = (uint32_t)(row * G2_AS + cc) * 2;
    }
    #pragma unroll
    for (int jj = 0; jj < 4; jj++) {   // B: 64 k-rows x 256 n (n-contig)
        int c = tid + jj * 512;
        int row = c >> 5;
        int cc = (c & 31) * 8;
        gB[jj]  = g_e16 + (size_t)row * E_DIM + bn + cc;
        soB[jj] = (uint32_t)(G2_APL + (row * G2_BS + cc) * 2);
    }

    auto load_stage = [&](int stg) {
        uint32_t sb = stb[stg];
        #pragma unroll
        for (int jj = 0; jj < 2; jj++) { cp16(sb + soA[jj], gA[jj]); gA[jj] += 64; }
        #pragma unroll
        for (int jj = 0; jj < 4; jj++) { cp16(sb + soB[jj], gB[jj]); gB[jj] += (size_t)64 * E_DIM; }
    };

    const int arow = wm * 32 + (lane & 15);
    const int csel = (lane >> 4) * 8;
    uint32_t foA[2], foB[4];
    #pragma unroll
    for (int i = 0; i < 2; i++)
        foA[i] = (uint32_t)(((arow + i * 16) * G2_AS + csel) * 2);
    #pragma unroll
    for (int jg = 0; jg < 4; jg++)
        foB[jg] = (uint32_t)(G2_APL + ((lane & 15) * G2_BS + wn * 64 + jg * 16 + csel) * 2);

    const int KT = V_DIM / 64;   // 500
    load_stage(0);  cp_commit();
    load_stage(1);  cp_commit();

    for (int t = 0; t < KT; t++) {
        cp_wait<1>();
        __syncthreads();
        if (t + 2 < KT) load_stage((t + 2) % 3);
        cp_commit();

        uint32_t sb = stb[t % 3];
        #pragma unroll
        for (int kk = 0; kk < 4; kk++) {
            uint32_t koA = kk * 32;
            uint32_t koB = kk * 16 * G2_BS * 2;
            uint32_t a[2][4], b[8][2];
            #pragma unroll
            for (int i = 0; i < 2; i++)
                ldsm4(a[i][0], a[i][1], a[i][2], a[i][3], sb + foA[i] + koA);
            #pragma unroll
            for (int jg = 0; jg < 4; jg++) {
                uint32_t r0, r1, r2, r3;
                ldsm4t(r0, r1, r2, r3, sb + foB[jg] + koB);
                b[2 * jg][0] = r0;      b[2 * jg][1] = r1;
                b[2 * jg + 1][0] = r2;  b[2 * jg + 1][1] = r3;
            }
            #pragma unroll
            for (int i = 0; i < 2; i++)
                #pragma unroll
                for (int j = 0; j < 8; j++)
                    mma_f16(acc[i][j], a[i], b[j]);
        }
    }

    const int g = lane >> 2, tq = lane & 3;
    #pragma unroll
    for (int i = 0; i < 2; i++) {
        int m0 = bm + wm * 32 + i * 16 + g;
        float s0 = 1.0f / g_sum[m0];
        float s1 = 1.0f / g_sum[m0 + 8];
        #pragma unroll
        for (int j = 0; j < 8; j++) {
            int n = bn + wn * 64 + j * 8 + tq * 2;
            float2 v0 = {acc[i][j][0] * s0, acc[i][j][1] * s0};
            float2 v1 = {acc[i][j][2] * s1, acc[i][j][3] * s1};
            *(float2*)&out[(size_t)m0 * E_DIM + n] = v0;
            *(float2*)&out[(size_t)(m0 + 8) * E_DIM + n] = v1;
        }
    }
}

// ---------------------------------------------------------------------------
extern "C" void kernel_launch(void* const* d_in, const int* in_sizes, int n_in,
                              void* d_out, int out_size)
{
    const float* asr = (const float*)d_in[0];
    const float* pw  = (const float*)d_in[1];
    const float* pb  = (const float*)d_in[2];
    const float* ew  = (const float*)d_in[3];
    float* out = (float*)d_out;
    (void)in_sizes; (void)n_in; (void)out_size;

    cudaFuncSetAttribute(gemm1_probs, cudaFuncAttributeMaxDynamicSharedMemorySize, G1_SMEM);
    cudaFuncSetAttribute(gemm2_map,   cudaFuncAttributeMaxDynamicSharedMemorySize, G2_SMEM);

    void *a16, *w16, *e16;
    cudaGetSymbolAddress(&a16, g_a16);
    cudaGetSymbolAddress(&w16, g_w16);
    cudaGetSymbolAddress(&e16, g_e16);

    cudaStream_t s2;
    cudaStreamCreateWithFlags(&s2, cudaStreamNonBlocking);
    cudaEvent_t eFork, eE;
    cudaEventCreateWithFlags(&eFork, cudaEventDisableTiming);
    cudaEventCreateWithFlags(&eE,    cudaEventDisableTiming);

    int nA = M_TOTAL * D_DIM / 4;
    int nW = V_DIM * D_DIM / 4;
    int nE = V_DIM * E_DIM / 4;

    // fork: conv_e16 (DRAM-bound) overlaps conv_a/conv_w/gemm1 (tensor-bound)
    cudaEventRecord(eFork, 0);
    cudaStreamWaitEvent(s2, eFork, 0);
    conv_f16<<<(nE + 255) / 256, 256, 0, s2>>>((const float4*)ew, (__half2*)e16, nE);
    cudaEventRecord(eE, s2);

    conv_a16<<<(nA + 255) / 256, 256>>>((const float4*)asr, (__half2*)a16, nA);
    conv_f16<<<(nW + 255) / 256, 256>>>((const float4*)pw,  (__half2*)w16, nW);
    gemm1_probs<<<(V_DIM / 256) * (M_TOTAL / 128), 512, G1_SMEM>>>(pb);

    cudaStreamWaitEvent(0, eE, 0);
    gemm2_map<<<(M_TOTAL / 128) * (E_DIM / 256), 512, G2_SMEM>>>(out);
}

// round 17
// speedup vs baseline: 1.0413x; 1.0413x over previous
#include <cuda_runtime.h>
#include <cuda_bf16.h>
#include <cuda_fp16.h>
#include <cstdint>

// out = softmax(A @ W^T + b) @ E
// GEMM1: fp16 mma.sync, 128x256x64, 16 warps, 32x64 warp tile (R16 best)
// GEMM2: fp16 mma.sync, 128x256x64, 8 warps, 64x64 warp tile, reg dbuf (R15 best)

#define M_TOTAL 8192
#define D_DIM   1024
#define V_DIM   32000
#define E_DIM   4096
#define SHIFT   8.0f

// ---------------- device scratch -------------------------------------------
__device__ __align__(1024) __half g_p[(size_t)M_TOTAL * V_DIM];
__device__ __align__(1024) float g_sum[M_TOTAL];
__device__ __align__(1024) __half g_a16[(size_t)M_TOTAL * D_DIM];
__device__ __align__(1024) __half g_w16[(size_t)V_DIM * D_DIM];
__device__ __align__(1024) __half g_e16[(size_t)V_DIM * E_DIM];

// ---------------- PTX helpers ----------------------------------------------
__device__ __forceinline__ uint32_t smem_u32(const void* p) {
    return (uint32_t)__cvta_generic_to_shared(p);
}
__device__ __forceinline__ void cp16(uint32_t s, const void* g) {
    asm volatile("cp.async.cg.shared.global [%0], [%1], 16;\n" :: "r"(s), "l"(g));
}
__device__ __forceinline__ void cp_commit() {
    asm volatile("cp.async.commit_group;\n");
}
template<int N>
__device__ __forceinline__ void cp_wait() {
    asm volatile("cp.async.wait_group %0;\n" :: "n"(N));
}
__device__ __forceinline__ void ldsm4(uint32_t& r0, uint32_t& r1, uint32_t& r2, uint32_t& r3, uint32_t addr) {
    asm volatile("ldmatrix.sync.aligned.m8n8.x4.shared.b16 {%0,%1,%2,%3}, [%4];\n"
                 : "=r"(r0), "=r"(r1), "=r"(r2), "=r"(r3) : "r"(addr));
}
__device__ __forceinline__ void ldsm4t(uint32_t& r0, uint32_t& r1, uint32_t& r2, uint32_t& r3, uint32_t addr) {
    asm volatile("ldmatrix.sync.aligned.m8n8.x4.trans.shared.b16 {%0,%1,%2,%3}, [%4];\n"
                 : "=r"(r0), "=r"(r1), "=r"(r2), "=r"(r3) : "r"(addr));
}
__device__ __forceinline__ void mma_f16(float* d, const uint32_t* a, const uint32_t* b) {
    asm volatile("mma.sync.aligned.m16n8k16.row.col.f32.f16.f16.f32 "
                 "{%0,%1,%2,%3}, {%4,%5,%6,%7}, {%8,%9}, {%0,%1,%2,%3};\n"
                 : "+f"(d[0]), "+f"(d[1]), "+f"(d[2]), "+f"(d[3])
                 : "r"(a[0]), "r"(a[1]), "r"(a[2]), "r"(a[3]), "r"(b[0]), "r"(b[1]));
}

// ---------------- prep kernels ----------------------------------------------
__global__ __launch_bounds__(256) void conv_a16(
    const float4* __restrict__ src, __half2* __restrict__ dst, int n4)
{
    int b = blockIdx.x;
    int i = b * 256 + threadIdx.x;
    if (b < 32) g_sum[i] = 0.0f;
    if (i >= n4) return;
    float4 v = src[i];
    dst[2*i]   = __floats2half2_rn(v.x, v.y);
    dst[2*i+1] = __floats2half2_rn(v.z, v.w);
}

__global__ __launch_bounds__(256) void conv_f16(
    const float4* __restrict__ src, __half2* __restrict__ dst, int n4)
{
    int i = blockIdx.x * 256 + threadIdx.x;
    if (i >= n4) return;
    float4 v = src[i];
    dst[2*i]   = __floats2half2_rn(v.x, v.y);
    dst[2*i+1] = __floats2half2_rn(v.z, v.w);
}

// ---------------- GEMM1: 128x256x64, 16 warps, 32x64 warp tile, fp16 --------
#define G1_AS 72                       // 64 k + 8 pad (elems)
#define G1_APL (128 * G1_AS * 2)       // 18432
#define G1_BPL (256 * G1_AS * 2)       // 36864
#define G1_STAGE_B (G1_APL + G1_BPL)   // 55296
#define G1_STAGES 3
#define G1_SMEM (G1_STAGES * G1_STAGE_B + 512)

__global__ __launch_bounds__(512, 1) void gemm1_probs(const float* __restrict__ bias)
{
    extern __shared__ char smem[];
    float* srow = (float*)(smem + G1_STAGES * G1_STAGE_B);

    const int tid = threadIdx.x;
    const int lane = tid & 31;
    const int warp = tid >> 5;
    const int wm = warp >> 2;     // 0..3 (32 m)
    const int wn = warp & 3;      // 0..3 (64 n)

    const int NB = V_DIM / 256;   // 125
    const int bid = blockIdx.x;
    const int strip = bid / (8 * NB);
    const int r = bid % (8 * NB);
    const int bm = (strip * 8 + (r & 7)) * 128;
    const int bn = (r >> 3) * 256;

    if (tid < 128) srow[tid] = 0.0f;

    float acc[2][8][4];
    #pragma unroll
    for (int i = 0; i < 2; i++)
        #pragma unroll
        for (int j = 0; j < 8; j++)
            #pragma unroll
            for (int q = 0; q < 4; q++) acc[i][j][q] = 0.0f;

    uint32_t stb[G1_STAGES];
    #pragma unroll
    for (int s = 0; s < G1_STAGES; s++) stb[s] = smem_u32(smem) + s * G1_STAGE_B;

    const __half* gA[2];
    const __half* gW[4];
    uint32_t soA[2], soW[4];
    #pragma unroll
    for (int jj = 0; jj < 2; jj++) {
        int c = tid + jj * 512;
        int row = c >> 3;
        int cc = (c & 7) * 8;
        gA[jj]  = g_a16 + (size_t)(bm + row) * D_DIM + cc;
        soA[jj] = (uint32_t)(row * G1_AS + cc) * 2;
    }
    #pragma unroll
    for (int jj = 0; jj < 4; jj++) {
        int c = tid + jj * 512;
        int row = c >> 3;
        int cc = (c & 7) * 8;
        gW[jj]  = g_w16 + (size_t)(bn + row) * D_DIM + cc;
        soW[jj] = (uint32_t)(G1_APL + (row * G1_AS + cc) * 2);
    }

    auto load_stage = [&](int stg) {
        uint32_t sb = stb[stg];
        #pragma unroll
        for (int jj = 0; jj < 2; jj++) { cp16(sb + soA[jj], gA[jj]); gA[jj] += 64; }
        #pragma unroll
        for (int jj = 0; jj < 4; jj++) { cp16(sb + soW[jj], gW[jj]); gW[jj] += 64; }
    };

    const int arow = wm * 32 + (lane & 15);
    const int brow = wn * 64 + (lane & 15);
    const int csel = (lane >> 4) * 8;
    uint32_t foA[2], foB[4];
    #pragma unroll
    for (int i = 0; i < 2; i++)
        foA[i] = (uint32_t)(((arow + i * 16) * G1_AS + csel) * 2);
    #pragma unroll
    for (int j = 0; j < 4; j++)
        foB[j] = (uint32_t)(G1_APL + ((brow + j * 16) * G1_AS + csel) * 2);

    const int KT = D_DIM / 64;   // 16
    load_stage(0);  cp_commit();
    load_stage(1);  cp_commit();

    for (int t = 0; t < KT; t++) {
        cp_wait<1>();
        __syncthreads();
        if (t + 2 < KT) load_stage((t + 2) % 3);
        cp_commit();

        uint32_t sb = stb[t % 3];
        #pragma unroll
        for (int kk = 0; kk < 4; kk++) {
            uint32_t ko = kk * 32;
            uint32_t a[2][4], b[8][2];
            #pragma unroll
            for (int i = 0; i < 2; i++)
                ldsm4(a[i][0], a[i][1], a[i][2], a[i][3], sb + foA[i] + ko);
            #pragma unroll
            for (int j = 0; j < 4; j++) {
                uint32_t r0, r1, r2, r3;
                ldsm4(r0, r1, r2, r3, sb + foB[j] + ko);
                b[2 * j][0] = r0;      b[2 * j + 1][0] = r1;
                b[2 * j][1] = r2;      b[2 * j + 1][1] = r3;
            }
            #pragma unroll
            for (int i = 0; i < 2; i++)
                #pragma unroll
                for (int j = 0; j < 8; j++)
                    mma_f16(acc[i][j], a[i], b[j]);
        }
    }
    __syncthreads();

    // fused epilogue: exp(logit - SHIFT) -> fp16 probs + row-sum atomics
    const int g = lane >> 2, tq = lane & 3;
    float bj0[8], bj1[8];
    #pragma unroll
    for (int j = 0; j < 8; j++) {
        int n = bn + wn * 64 + j * 8 + tq * 2;
        bj0[j] = bias[n];
        bj1[j] = bias[n + 1];
    }
    #pragma unroll
    for (int i = 0; i < 2; i++) {
        int ml0 = wm * 32 + i * 16 + g;
        float s0 = 0.0f, s1 = 0.0f;
        #pragma unroll
        for (int j = 0; j < 8; j++) {
            int n = bn + wn * 64 + j * 8 + tq * 2;
            float e0 = __expf(acc[i][j][0] + bj0[j] - SHIFT);
            float e1 = __expf(acc[i][j][1] + bj1[j] - SHIFT);
            float e2 = __expf(acc[i][j][2] + bj0[j] - SHIFT);
            float e3 = __expf(acc[i][j][3] + bj1[j] - SHIFT);
            s0 += e0 + e1;
            s1 += e2 + e3;
            *(__half2*)&g_p[(size_t)(bm + ml0) * V_DIM + n]     = __floats2half2_rn(e0, e1);
            *(__half2*)&g_p[(size_t)(bm + ml0 + 8) * V_DIM + n] = __floats2half2_rn(e2, e3);
        }
        s0 += __shfl_xor_sync(0xffffffff, s0, 1);
        s0 += __shfl_xor_sync(0xffffffff, s0, 2);
        s1 += __shfl_xor_sync(0xffffffff, s1, 1);
        s1 += __shfl_xor_sync(0xffffffff, s1, 2);
        if (tq == 0) {
            atomicAdd(&srow[ml0], s0);
            atomicAdd(&srow[ml0 + 8], s1);
        }
    }
    __syncthreads();
    if (tid < 128) atomicAdd(&g_sum[bm + tid], srow[tid]);
}

// ---------------- GEMM2: 128x256x64, 8 warps, 64x64 warp tile, reg dbuf -----
#define G2_AS 72
#define G2_APL (128 * G2_AS * 2)       // 18432
#define G2_BS 264                      // 256 n + 8 pad
#define G2_BPL (64 * G2_BS * 2)        // 33792
#define G2_STAGE_B (G2_APL + G2_BPL)   // 52224
#define G2_STAGES 3
#define G2_SMEM (G2_STAGES * G2_STAGE_B)

__global__ __launch_bounds__(256, 1) void gemm2_map(float* __restrict__ out)
{
    extern __shared__ char smem[];
    const int tid = threadIdx.x;
    const int lane = tid & 31;
    const int warp = tid >> 5;
    const int wm = warp >> 2;     // 0..1
    const int wn = warp & 3;      // 0..3

    const int bid = blockIdx.x;
    const int strip = bid >> 7;
    const int r = bid & 127;
    const int bm = (strip * 8 + (r & 7)) * 128;
    const int bn = (r >> 3) * 256;

    float acc[4][8][4];
    #pragma unroll
    for (int i = 0; i < 4; i++)
        #pragma unroll
        for (int j = 0; j < 8; j++)
            #pragma unroll
            for (int q = 0; q < 4; q++) acc[i][j][q] = 0.0f;

    uint32_t stb[G2_STAGES];
    #pragma unroll
    for (int s = 0; s < G2_STAGES; s++) stb[s] = smem_u32(smem) + s * G2_STAGE_B;

    const __half* gA[4];
    const __half* gB[8];
    uint32_t soA[4], soB[8];
    #pragma unroll
    for (int jj = 0; jj < 4; jj++) {   // A: 128 rows x 64 k (k-contig)
        int c = tid + jj * 256;
        int row = c >> 3;
        int cc = (c & 7) * 8;
        gA[jj]  = g_p + (size_t)(bm + row) * V_DIM + cc;
        soA[jj] = (uint32_t)(row * G2_AS + cc) * 2;
    }
    #pragma unroll
    for (int jj = 0; jj < 8; jj++) {   // B: 64 k-rows x 256 n (n-contig)
        int c = tid + jj * 256;
        int row = c >> 5;
        int cc = (c & 31) * 8;
        gB[jj]  = g_e16 + (size_t)row * E_DIM + bn + cc;
        soB[jj] = (uint32_t)(G2_APL + (row * G2_BS + cc) * 2);
    }

    auto load_stage = [&](int stg) {
        uint32_t sb = stb[stg];
        #pragma unroll
        for (int jj = 0; jj < 4; jj++) { cp16(sb + soA[jj], gA[jj]); gA[jj] += 64; }
        #pragma unroll
        for (int jj = 0; jj < 8; jj++) { cp16(sb + soB[jj], gB[jj]); gB[jj] += (size_t)64 * E_DIM; }
    };

    const int arow = wm * 64 + (lane & 15);
    const int csel = (lane >> 4) * 8;
    uint32_t foA[4], foB[4];
    #pragma unroll
    for (int i = 0; i < 4; i++)
        foA[i] = (uint32_t)(((arow + i * 16) * G2_AS + csel) * 2);
    #pragma unroll
    for (int jg = 0; jg < 4; jg++)
        foB[jg] = (uint32_t)(G2_APL + ((lane & 15) * G2_BS + wn * 64 + jg * 16 + csel) * 2);

    auto ld_frags = [&](uint32_t sb, int kk, uint32_t a[4][4], uint32_t b[8][2]) {
        uint32_t koA = kk * 32;
        uint32_t koB = kk * 16 * G2_BS * 2;
        #pragma unroll
        for (int i = 0; i < 4; i++)
            ldsm4(a[i][0], a[i][1], a[i][2], a[i][3], sb + foA[i] + koA);
        #pragma unroll
        for (int jg = 0; jg < 4; jg++) {
            uint32_t r0, r1, r2, r3;
            ldsm4t(r0, r1, r2, r3, sb + foB[jg] + koB);
            b[2 * jg][0] = r0;      b[2 * jg][1] = r1;
            b[2 * jg + 1][0] = r2;  b[2 * jg + 1][1] = r3;
        }
    };

    const int KT = V_DIM / 64;   // 500
    load_stage(0);  cp_commit();
    load_stage(1);  cp_commit();

    uint32_t af[2][4][4], bf[2][8][2];

    for (int t = 0; t < KT; t++) {
        cp_wait<1>();
        __syncthreads();
        if (t + 2 < KT) load_stage((t + 2) % 3);
        cp_commit();

        uint32_t sb = stb[t % 3];
        ld_frags(sb, 0, af[0], bf[0]);
        #pragma unroll
        for (int kk = 0; kk < 4; kk++) {
            int cur = kk & 1;
            if (kk < 3) ld_frags(sb, kk + 1, af[cur ^ 1], bf[cur ^ 1]);
            #pragma unroll
            for (int i = 0; i < 4; i++)
                #pragma unroll
                for (int j = 0; j < 8; j++)
                    mma_f16(acc[i][j], af[cur][i], bf[cur][j]);
        }
    }

    const int g = lane >> 2, tq = lane & 3;
    #pragma unroll
    for (int i = 0; i < 4; i++) {
        int m0 = bm + wm * 64 + i * 16 + g;
        float s0 = 1.0f / g_sum[m0];
        float s1 = 1.0f / g_sum[m0 + 8];
        #pragma unroll
        for (int j = 0; j < 8; j++) {
            int n = bn + wn * 64 + j * 8 + tq * 2;
            float2 v0 = {acc[i][j][0] * s0, acc[i][j][1] * s0};
            float2 v1 = {acc[i][j][2] * s1, acc[i][j][3] * s1};
            *(float2*)&out[(size_t)m0 * E_DIM + n] = v0;
            *(float2*)&out[(size_t)(m0 + 8) * E_DIM + n] = v1;
        }
    }
}

// ---------------------------------------------------------------------------
extern "C" void kernel_launch(void* const* d_in, const int* in_sizes, int n_in,
                              void* d_out, int out_size)
{
    const float* asr = (const float*)d_in[0];
    const float* pw  = (const float*)d_in[1];
    const float* pb  = (const float*)d_in[2];
    const float* ew  = (const float*)d_in[3];
    float* out = (float*)d_out;
    (void)in_sizes; (void)n_in; (void)out_size;

    cudaFuncSetAttribute(gemm1_probs, cudaFuncAttributeMaxDynamicSharedMemorySize, G1_SMEM);
    cudaFuncSetAttribute(gemm2_map,   cudaFuncAttributeMaxDynamicSharedMemorySize, G2_SMEM);

    void *a16, *w16, *e16;
    cudaGetSymbolAddress(&a16, g_a16);
    cudaGetSymbolAddress(&w16, g_w16);
    cudaGetSymbolAddress(&e16, g_e16);

    cudaStream_t s2;
    cudaStreamCreateWithFlags(&s2, cudaStreamNonBlocking);
    cudaEvent_t eFork, eE;
    cudaEventCreateWithFlags(&eFork, cudaEventDisableTiming);
    cudaEventCreateWithFlags(&eE,    cudaEventDisableTiming);

    int nA = M_TOTAL * D_DIM / 4;
    int nW = V_DIM * D_DIM / 4;
    int nE = V_DIM * E_DIM / 4;

    // fork: conv_e16 (DRAM-bound) overlaps conv_a/conv_w/gemm1 (tensor-bound)
    cudaEventRecord(eFork, 0);
    cudaStreamWaitEvent(s2, eFork, 0);
    conv_f16<<<(nE + 255) / 256, 256, 0, s2>>>((const float4*)ew, (__half2*)e16, nE);
    cudaEventRecord(eE, s2);

    conv_a16<<<(nA + 255) / 256, 256>>>((const float4*)asr, (__half2*)a16, nA);
    conv_f16<<<(nW + 255) / 256, 256>>>((const float4*)pw,  (__half2*)w16, nW);
    gemm1_probs<<<(V_DIM / 256) * (M_TOTAL / 128), 512, G1_SMEM>>>(pb);

    cudaStreamWaitEvent(0, eE, 0);
    gemm2_map<<<(M_TOTAL / 128) * (E_DIM / 256), 256, G2_SMEM>>>(out);
}